// round 1
// baseline (speedup 1.0000x reference)
#include <cuda_runtime.h>
#include <math.h>

// ---------------- problem constants ----------------
namespace {
constexpr int kB = 2, kCIN = 3, kIMG = 384, kP = 16;
constexpr int kD = 1024, kH = 16, kHD = 64, kDEPTH = 24;
constexpr int kGH = 24, kNP = 576, kN = 577, kDFF = 4096;
constexpr int kM = kB * kN;          // 1154 token rows
constexpr int kKP = kCIN * kP * kP;  // 768 patch K
constexpr float kScale = 0.125f;     // HD^-0.5
}

// ---------------- scratch (device globals; no allocs allowed) ----------------
__device__ float g_h[kM * kD];
__device__ float g_y[kM * kD];
__device__ float g_qkv[kM * 3 * kD];
__device__ float g_att[(size_t)kB * kH * kN * kN];
__device__ float g_o[kM * kD];
__device__ float g_hid[(size_t)kM * kDFF];
__device__ float g_wpT[kKP * kD];
__device__ float g_col[kB * kNP * kKP];

// ---------------- tiled fp32 GEMM: C[M,N] = op(A[M,K] @ B[K,N] + bias [+R]) ----------------
enum { EP_BIAS = 0, EP_RESID = 1, EP_GELU = 2 };

template <int EP>
__global__ __launch_bounds__(256) void gemm128(
    const float* __restrict__ A, const float* __restrict__ Bw,
    const float* __restrict__ bias, const float* __restrict__ R,
    float* __restrict__ C, int M, int N, int K)
{
    __shared__ float As[8][128];   // transposed A tile
    __shared__ float Bs[8][128];
    const int tid = threadIdx.x;
    const int m0 = blockIdx.y * 128, n0 = blockIdx.x * 128;
    const int tx = tid & 15, ty = tid >> 4;

    const int a_row = tid >> 1;            // 0..127
    const int a_f4  = (tid & 1) * 4;       // 0 or 4
    const int b_row = tid >> 5;            // 0..7
    const int b_col = (tid & 31) * 4;      // 0..124

    float acc[8][8];
#pragma unroll
    for (int i = 0; i < 8; i++)
#pragma unroll
        for (int j = 0; j < 8; j++) acc[i][j] = 0.f;

    for (int k0 = 0; k0 < K; k0 += 8) {
        float4 av;
        if (m0 + a_row < M)
            av = *reinterpret_cast<const float4*>(&A[(size_t)(m0 + a_row) * K + k0 + a_f4]);
        else
            av = make_float4(0.f, 0.f, 0.f, 0.f);
        As[a_f4 + 0][a_row] = av.x;
        As[a_f4 + 1][a_row] = av.y;
        As[a_f4 + 2][a_row] = av.z;
        As[a_f4 + 3][a_row] = av.w;

        float4 bv = *reinterpret_cast<const float4*>(&Bw[(size_t)(k0 + b_row) * N + n0 + b_col]);
        *reinterpret_cast<float4*>(&Bs[b_row][b_col]) = bv;

        __syncthreads();
#pragma unroll
        for (int kk = 0; kk < 8; kk++) {
            float ar[8], br[8];
            *reinterpret_cast<float4*>(ar)     = *reinterpret_cast<const float4*>(&As[kk][ty * 8]);
            *reinterpret_cast<float4*>(ar + 4) = *reinterpret_cast<const float4*>(&As[kk][ty * 8 + 4]);
            *reinterpret_cast<float4*>(br)     = *reinterpret_cast<const float4*>(&Bs[kk][tx * 8]);
            *reinterpret_cast<float4*>(br + 4) = *reinterpret_cast<const float4*>(&Bs[kk][tx * 8 + 4]);
#pragma unroll
            for (int i = 0; i < 8; i++)
#pragma unroll
                for (int j = 0; j < 8; j++) acc[i][j] += ar[i] * br[j];
        }
        __syncthreads();
    }

#pragma unroll
    for (int i = 0; i < 8; i++) {
        int row = m0 + ty * 8 + i;
        if (row >= M) continue;
#pragma unroll
        for (int j = 0; j < 8; j++) {
            int col = n0 + tx * 8 + j;
            if (col >= N) continue;
            float v = acc[i][j] + bias[col];
            if (EP == EP_RESID) v += R[(size_t)row * N + col];
            if (EP == EP_GELU)  v = 0.5f * v * (1.f + erff(v * 0.70710678118654752f));
            C[(size_t)row * N + col] = v;
        }
    }
}

// ---------------- attention scores: att[b,h,n,m] = scale * q·k ----------------
__global__ __launch_bounds__(256) void attn_scores_k(
    const float* __restrict__ qkv, float* __restrict__ att)
{
    const int bh = blockIdx.z;
    const int b = bh >> 4, h = bh & 15;
    const int n0 = blockIdx.y * 64, m0 = blockIdx.x * 64;
    const float* qb = qkv + (size_t)(b * kN) * 3 * kD + h * kHD;
    const float* kb = qb + kD;

    __shared__ float As[16][64], Bs[16][64];
    const int tid = threadIdx.x;
    const int tx = tid & 15, ty = tid >> 4;
    float acc[4][4] = {};

    for (int k0 = 0; k0 < kHD; k0 += 16) {
#pragma unroll
        for (int i = 0; i < 4; i++) {
            int idx = tid + i * 256;
            int r = idx >> 4, k = idx & 15;
            As[k][r] = (n0 + r < kN) ? qb[(size_t)(n0 + r) * (3 * kD) + k0 + k] : 0.f;
            Bs[k][r] = (m0 + r < kN) ? kb[(size_t)(m0 + r) * (3 * kD) + k0 + k] : 0.f;
        }
        __syncthreads();
#pragma unroll
        for (int kk = 0; kk < 16; kk++) {
            float ar[4], br[4];
#pragma unroll
            for (int i = 0; i < 4; i++) { ar[i] = As[kk][ty * 4 + i]; br[i] = Bs[kk][tx * 4 + i]; }
#pragma unroll
            for (int i = 0; i < 4; i++)
#pragma unroll
                for (int j = 0; j < 4; j++) acc[i][j] += ar[i] * br[j];
        }
        __syncthreads();
    }

    float* ob = att + (size_t)bh * kN * kN;
#pragma unroll
    for (int i = 0; i < 4; i++) {
        int n = n0 + ty * 4 + i;
        if (n >= kN) continue;
#pragma unroll
        for (int j = 0; j < 4; j++) {
            int m = m0 + tx * 4 + j;
            if (m >= kN) continue;
            ob[(size_t)n * kN + m] = acc[i][j] * kScale;
        }
    }
}

// ---------------- softmax over last dim (rows of length kN) ----------------
__global__ __launch_bounds__(256) void softmax_k(float* __restrict__ att)
{
    float* p = att + (size_t)blockIdx.x * kN;
    const int tid = threadIdx.x;
    __shared__ float red[256];

    float m = -1e30f;
    for (int i = tid; i < kN; i += 256) m = fmaxf(m, p[i]);
    red[tid] = m; __syncthreads();
    for (int s = 128; s > 0; s >>= 1) { if (tid < s) red[tid] = fmaxf(red[tid], red[tid + s]); __syncthreads(); }
    m = red[0]; __syncthreads();

    float s = 0.f;
    for (int i = tid; i < kN; i += 256) { float e = __expf(p[i] - m); p[i] = e; s += e; }
    red[tid] = s; __syncthreads();
    for (int st = 128; st > 0; st >>= 1) { if (tid < st) red[tid] += red[tid + st]; __syncthreads(); }
    float inv = 1.f / red[0];
    for (int i = tid; i < kN; i += 256) p[i] *= inv;
}

// ---------------- o[b,n,h,:] = att[b,h,n,:] @ v[b,:,h,:] ----------------
__global__ __launch_bounds__(256) void attn_av_k(
    const float* __restrict__ att, const float* __restrict__ qkv, float* __restrict__ o)
{
    const int bh = blockIdx.z;
    const int b = bh >> 4, h = bh & 15;
    const int n0 = blockIdx.y * 64;
    const float* ab = att + (size_t)bh * kN * kN;
    const float* vb = qkv + (size_t)(b * kN) * 3 * kD + 2 * kD + h * kHD;

    __shared__ float As[16][64], Bs[16][64];
    const int tid = threadIdx.x;
    const int tx = tid & 15, ty = tid >> 4;
    float acc[4][4] = {};

    for (int k0 = 0; k0 < kN; k0 += 16) {
#pragma unroll
        for (int i = 0; i < 4; i++) {
            int idx = tid + i * 256;
            int r = idx >> 4, k = idx & 15;
            As[k][r] = (n0 + r < kN && k0 + k < kN) ? ab[(size_t)(n0 + r) * kN + k0 + k] : 0.f;
            int kr = idx >> 6, hd = idx & 63;
            Bs[kr][hd] = (k0 + kr < kN) ? vb[(size_t)(k0 + kr) * (3 * kD) + hd] : 0.f;
        }
        __syncthreads();
#pragma unroll
        for (int kk = 0; kk < 16; kk++) {
            float ar[4], br[4];
#pragma unroll
            for (int i = 0; i < 4; i++) { ar[i] = As[kk][ty * 4 + i]; br[i] = Bs[kk][tx * 4 + i]; }
#pragma unroll
            for (int i = 0; i < 4; i++)
#pragma unroll
                for (int j = 0; j < 4; j++) acc[i][j] += ar[i] * br[j];
        }
        __syncthreads();
    }

#pragma unroll
    for (int i = 0; i < 4; i++) {
        int n = n0 + ty * 4 + i;
        if (n >= kN) continue;
#pragma unroll
        for (int j = 0; j < 4; j++) {
            int hd = tx * 4 + j;
            o[(size_t)(b * kN + n) * kD + h * kHD + hd] = acc[i][j];
        }
    }
}

// ---------------- layernorm (row length kD=1024, 256 threads x 4) ----------------
__global__ __launch_bounds__(256) void ln_k(
    const float* __restrict__ x, const float* __restrict__ g,
    const float* __restrict__ bb, float* __restrict__ y)
{
    const int row = blockIdx.x, tid = threadIdx.x;
    const float* xr = x + (size_t)row * kD;
    float v[4]; float s = 0.f;
#pragma unroll
    for (int i = 0; i < 4; i++) { v[i] = xr[tid + i * 256]; s += v[i]; }
    __shared__ float red[256];
    red[tid] = s; __syncthreads();
    for (int st = 128; st > 0; st >>= 1) { if (tid < st) red[tid] += red[tid + st]; __syncthreads(); }
    float mean = red[0] * (1.f / kD); __syncthreads();
    float sq = 0.f;
#pragma unroll
    for (int i = 0; i < 4; i++) { float d = v[i] - mean; sq += d * d; }
    red[tid] = sq; __syncthreads();
    for (int st = 128; st > 0; st >>= 1) { if (tid < st) red[tid] += red[tid + st]; __syncthreads(); }
    float inv = rsqrtf(red[0] * (1.f / kD) + 1e-6f);
    float* yr = y + (size_t)row * kD;
#pragma unroll
    for (int i = 0; i < 4; i++) { int c = tid + i * 256; yr[c] = (v[i] - mean) * inv * g[c] + bb[c]; }
}

// ---------------- small helpers ----------------
__global__ void im2col_k(const float* __restrict__ x, float* __restrict__ col)
{
    int idx = blockIdx.x * 256 + threadIdx.x;
    if (idx >= kB * kNP * kKP) return;
    int kk = idx % kKP; int m = idx / kKP;
    int b = m / kNP; int pi = m % kNP;
    int gh = pi / kGH; int gw = pi % kGH;
    int c = kk / (kP * kP); int rr = (kk % (kP * kP)) / kP; int q = kk % kP;
    col[idx] = x[(((size_t)b * kCIN + c) * kIMG + gh * kP + rr) * kIMG + gw * kP + q];
}

__global__ void wpt_k(const float* __restrict__ Wp, float* __restrict__ wt)
{
    int idx = blockIdx.x * 256 + threadIdx.x;
    if (idx >= kKP * kD) return;
    int d = idx % kD; int k = idx / kD;
    wt[idx] = Wp[(size_t)d * kKP + k];
}

__global__ void assemble_k(const float* __restrict__ tok, const float* __restrict__ cls,
                           const float* __restrict__ pos, float* __restrict__ h)
{
    int idx = blockIdx.x * 256 + threadIdx.x;
    if (idx >= kM * kD) return;
    int d = idx % kD; int rem = idx / kD; int n = rem % kN; int b = rem / kN;
    float v = (n == 0) ? cls[d] : tok[((size_t)b * kNP + (n - 1)) * kD + d];
    h[idx] = v + pos[(size_t)n * kD + d];
}

__global__ void copy_k(const float* __restrict__ src, float* __restrict__ dst, int n)
{
    int idx = blockIdx.x * 256 + threadIdx.x;
    if (idx < n) dst[idx] = src[idx];
}

// ---------------- launch ----------------
extern "C" void kernel_launch(void* const* d_in, const int* in_sizes, int n_in,
                              void* d_out, int out_size)
{
    (void)in_sizes; (void)n_in; (void)out_size;
    const float* x    = (const float*)d_in[0];
    const float* Wp   = (const float*)d_in[1];
    const float* bp   = (const float*)d_in[2];
    const float* cls  = (const float*)d_in[3];
    const float* pos  = (const float*)d_in[4];
    const float* g1   = (const float*)d_in[5];
    const float* b1   = (const float*)d_in[6];
    const float* Wqkv = (const float*)d_in[7];
    const float* bqkv = (const float*)d_in[8];
    const float* Wo   = (const float*)d_in[9];
    const float* bo   = (const float*)d_in[10];
    const float* g2   = (const float*)d_in[11];
    const float* b2   = (const float*)d_in[12];
    const float* W1   = (const float*)d_in[13];
    const float* b1m  = (const float*)d_in[14];
    const float* W2   = (const float*)d_in[15];
    const float* b2m  = (const float*)d_in[16];

    float *h, *y, *qkv, *att, *o, *hid, *wpT, *colb;
    cudaGetSymbolAddress((void**)&h,    g_h);
    cudaGetSymbolAddress((void**)&y,    g_y);
    cudaGetSymbolAddress((void**)&qkv,  g_qkv);
    cudaGetSymbolAddress((void**)&att,  g_att);
    cudaGetSymbolAddress((void**)&o,    g_o);
    cudaGetSymbolAddress((void**)&hid,  g_hid);
    cudaGetSymbolAddress((void**)&wpT,  g_wpT);
    cudaGetSymbolAddress((void**)&colb, g_col);

    // patch embed
    {
        int total = kB * kNP * kKP;
        im2col_k<<<(total + 255) / 256, 256>>>(x, colb);
    }
    {
        int total = kKP * kD;
        wpt_k<<<(total + 255) / 256, 256>>>(Wp, wpT);
    }
    {
        dim3 grid(kD / 128, (kB * kNP + 127) / 128);
        gemm128<EP_BIAS><<<grid, 256>>>(colb, wpT, bp, nullptr, y, kB * kNP, kD, kKP);
    }
    {
        int total = kM * kD;
        assemble_k<<<(total + 255) / 256, 256>>>(y, cls, pos, h);
    }

    // transformer blocks
    for (int l = 0; l < kDEPTH; l++) {
        ln_k<<<kM, 256>>>(h, g1 + (size_t)l * kD, b1 + (size_t)l * kD, y);
        {
            dim3 grid(3 * kD / 128, (kM + 127) / 128);
            gemm128<EP_BIAS><<<grid, 256>>>(y, Wqkv + (size_t)l * kD * 3 * kD,
                                            bqkv + (size_t)l * 3 * kD, nullptr, qkv,
                                            kM, 3 * kD, kD);
        }
        {
            dim3 grid((kN + 63) / 64, (kN + 63) / 64, kB * kH);
            attn_scores_k<<<grid, 256>>>(qkv, att);
        }
        softmax_k<<<kB * kH * kN, 256>>>(att);
        {
            dim3 grid(1, (kN + 63) / 64, kB * kH);
            attn_av_k<<<grid, 256>>>(att, qkv, o);
        }
        {
            dim3 grid(kD / 128, (kM + 127) / 128);
            gemm128<EP_RESID><<<grid, 256>>>(o, Wo + (size_t)l * kD * kD,
                                             bo + (size_t)l * kD, h, h, kM, kD, kD);
        }
        ln_k<<<kM, 256>>>(h, g2 + (size_t)l * kD, b2 + (size_t)l * kD, y);
        {
            dim3 grid(kDFF / 128, (kM + 127) / 128);
            gemm128<EP_GELU><<<grid, 256>>>(y, W1 + (size_t)l * kD * kDFF,
                                            b1m + (size_t)l * kDFF, nullptr, hid,
                                            kM, kDFF, kD);
        }
        {
            dim3 grid(kD / 128, (kM + 127) / 128);
            gemm128<EP_RESID><<<grid, 256>>>(hid, W2 + (size_t)l * kDFF * kD,
                                             b2m + (size_t)l * kD, h, h, kM, kD, kDFF);
        }
    }

    {
        int total = kM * kD;
        copy_k<<<(total + 255) / 256, 256>>>(h, (float*)d_out, total);
    }
}

// round 2
// speedup vs baseline: 2.1160x; 2.1160x over previous
#include <cuda_runtime.h>
#include <math.h>

// ---------------- problem constants ----------------
namespace {
constexpr int kB = 2, kCIN = 3, kIMG = 384, kP = 16;
constexpr int kD = 1024, kH = 16, kHD = 64, kDEPTH = 24;
constexpr int kGH = 24, kNP = 576, kN = 577, kDFF = 4096;
constexpr int kM = kB * kN;          // 1154 token rows
constexpr int kKP = kCIN * kP * kP;  // 768 patch K
constexpr int kNpad = 608;           // att row stride, 19*32 (ragged-free K for AV)
constexpr float kScale = 0.125f;     // HD^-0.5
}

// ---------------- scratch (device globals; no allocs allowed) ----------------
__device__ float g_h[kM * kD];
__device__ float g_y[kM * kD];
__device__ float g_qkv[(kM + 32) * 3 * kD];   // +32 pad rows (read as zeros by AV K-pad)
__device__ float g_att[(size_t)kB * kH * kN * kNpad];
__device__ float g_o[kM * kD];
__device__ float g_hid[(size_t)kM * kDFF];
__device__ float g_wpT[kKP * kD];
__device__ float g_col[kB * kNP * kKP];

// ---------------- tf32 helpers ----------------
__device__ __forceinline__ unsigned f2tf(float f) {
    unsigned r;
    asm("cvt.rna.tf32.f32 %0, %1;" : "=r"(r) : "f"(f));
    return r;
}

__device__ __forceinline__ void mma_tf32(float c[4], unsigned a0, unsigned a1,
                                         unsigned a2, unsigned a3,
                                         unsigned b0, unsigned b1) {
    asm volatile(
        "mma.sync.aligned.m16n8k8.row.col.f32.tf32.tf32.f32 "
        "{%0,%1,%2,%3}, {%4,%5,%6,%7}, {%8,%9}, {%0,%1,%2,%3};"
        : "+f"(c[0]), "+f"(c[1]), "+f"(c[2]), "+f"(c[3])
        : "r"(a0), "r"(a1), "r"(a2), "r"(a3), "r"(b0), "r"(b1));
}

// ---------------- unified TF32 tensor-core GEMM ----------------
// C[M,N] = epilogue( A[M,K] @ B[K,N] )   (TRANSB: B given as [N,K] row-major)
// Batched via blockIdx.z with (z/zdiv, z%zdiv) strides.
enum { EP_NONE = 0, EP_SCALE = 1, EP_BIAS = 2, EP_RESID = 3, EP_GELU = 4 };

constexpr int AS_STRIDE = 36;   // 32 k + 4 pad  (frag banks = 4g+t : conflict-free)
constexpr int BS_STRIDE = 136;  // 128 n + 8 pad (frag banks = 8t+g : conflict-free)

template <int EP, bool TRANSB>
__global__ __launch_bounds__(256) void mm_tf32(
    const float* __restrict__ A, int lda, long sAb, long sAh,
    const float* __restrict__ Bg, int ldb, long sBb, long sBh,
    const float* __restrict__ bias, const float* __restrict__ R,
    float* __restrict__ C, int ldc, long sCb, long sCh,
    int M, int N, int K, int zdiv, float alpha)
{
    __shared__ float As[128 * AS_STRIDE];
    __shared__ float Bs[32 * BS_STRIDE];

    const int tid = threadIdx.x;
    const int z = blockIdx.z;
    const int zb = z / zdiv, zh = z % zdiv;
    const float* Ab = A + zb * sAb + zh * sAh;
    const float* Bb = Bg + zb * sBb + zh * sBh;
    const float* Rb = R ? (R + zb * sCb + zh * sCh) : nullptr;
    float* Cb = C + zb * sCb + zh * sCh;

    const int m0 = blockIdx.y * 128, n0 = blockIdx.x * 128;
    const int wid = tid >> 5, lane = tid & 31;
    const int wm = (wid & 1) * 64, wn = (wid >> 1) * 32;
    const int g = lane >> 2, t = lane & 3;

    float acc[4][4][4];
#pragma unroll
    for (int i = 0; i < 4; i++)
#pragma unroll
        for (int j = 0; j < 4; j++)
#pragma unroll
            for (int e = 0; e < 4; e++) acc[i][j][e] = 0.f;

    for (int k0 = 0; k0 < K; k0 += 32) {
        // ---- load A tile 128x32 ----
        {
            const int r = tid >> 3, cq = (tid & 7) * 4;
#pragma unroll
            for (int p = 0; p < 4; p++) {
                int row = r + p * 32;
                float4 v = make_float4(0.f, 0.f, 0.f, 0.f);
                if (m0 + row < M)
                    v = *reinterpret_cast<const float4*>(&Ab[(size_t)(m0 + row) * lda + k0 + cq]);
                float4 w;
                w.x = __uint_as_float(f2tf(v.x));
                w.y = __uint_as_float(f2tf(v.y));
                w.z = __uint_as_float(f2tf(v.z));
                w.w = __uint_as_float(f2tf(v.w));
                *reinterpret_cast<float4*>(&As[row * AS_STRIDE + cq]) = w;
            }
        }
        // ---- load B tile 32x128 ----
        if (TRANSB) {
            const int r = tid >> 3, cq = (tid & 7) * 4;
#pragma unroll
            for (int p = 0; p < 4; p++) {
                int nloc = r + p * 32;
                float4 v = make_float4(0.f, 0.f, 0.f, 0.f);
                if (n0 + nloc < N)
                    v = *reinterpret_cast<const float4*>(&Bb[(size_t)(n0 + nloc) * ldb + k0 + cq]);
                Bs[(cq + 0) * BS_STRIDE + nloc] = __uint_as_float(f2tf(v.x));
                Bs[(cq + 1) * BS_STRIDE + nloc] = __uint_as_float(f2tf(v.y));
                Bs[(cq + 2) * BS_STRIDE + nloc] = __uint_as_float(f2tf(v.z));
                Bs[(cq + 3) * BS_STRIDE + nloc] = __uint_as_float(f2tf(v.w));
            }
        } else {
            const int c = lane * 4;
#pragma unroll
            for (int p = 0; p < 4; p++) {
                int kr = (tid >> 5) + p * 8;
                const float* src = &Bb[(size_t)(k0 + kr) * ldb + n0 + c];
                float4 v;
                if (n0 + c + 3 < N) {
                    v = *reinterpret_cast<const float4*>(src);
                } else {
                    v.x = (n0 + c + 0 < N) ? src[0] : 0.f;
                    v.y = (n0 + c + 1 < N) ? src[1] : 0.f;
                    v.z = (n0 + c + 2 < N) ? src[2] : 0.f;
                    v.w = (n0 + c + 3 < N) ? src[3] : 0.f;
                }
                float4 w;
                w.x = __uint_as_float(f2tf(v.x));
                w.y = __uint_as_float(f2tf(v.y));
                w.z = __uint_as_float(f2tf(v.z));
                w.w = __uint_as_float(f2tf(v.w));
                *reinterpret_cast<float4*>(&Bs[kr * BS_STRIDE + c]) = w;
            }
        }
        __syncthreads();

#pragma unroll
        for (int ks = 0; ks < 4; ks++) {
            unsigned bf[4][2];
#pragma unroll
            for (int nt = 0; nt < 4; nt++) {
                int ncol = wn + nt * 8 + g;
                bf[nt][0] = __float_as_uint(Bs[(ks * 8 + t) * BS_STRIDE + ncol]);
                bf[nt][1] = __float_as_uint(Bs[(ks * 8 + t + 4) * BS_STRIDE + ncol]);
            }
#pragma unroll
            for (int mt = 0; mt < 4; mt++) {
                int rowa = wm + mt * 16 + g;
                unsigned a0 = __float_as_uint(As[rowa * AS_STRIDE + ks * 8 + t]);
                unsigned a1 = __float_as_uint(As[(rowa + 8) * AS_STRIDE + ks * 8 + t]);
                unsigned a2 = __float_as_uint(As[rowa * AS_STRIDE + ks * 8 + t + 4]);
                unsigned a3 = __float_as_uint(As[(rowa + 8) * AS_STRIDE + ks * 8 + t + 4]);
#pragma unroll
                for (int nt = 0; nt < 4; nt++)
                    mma_tf32(acc[mt][nt], a0, a1, a2, a3, bf[nt][0], bf[nt][1]);
            }
        }
        __syncthreads();
    }

    // ---- epilogue ----
#pragma unroll
    for (int mt = 0; mt < 4; mt++) {
#pragma unroll
        for (int rr = 0; rr < 2; rr++) {
            int row = m0 + wm + mt * 16 + g + rr * 8;
            if (row >= M) continue;
#pragma unroll
            for (int nt = 0; nt < 4; nt++) {
                int col = n0 + wn + nt * 8 + 2 * t;
#pragma unroll
                for (int e = 0; e < 2; e++) {
                    int c = col + e;
                    if (c >= N) continue;
                    float v = acc[mt][nt][rr * 2 + e];
                    if (EP == EP_SCALE) v *= alpha;
                    if (EP == EP_BIAS || EP == EP_RESID || EP == EP_GELU) v += bias[c];
                    if (EP == EP_RESID) v += Rb[(size_t)row * ldc + c];
                    if (EP == EP_GELU) v = 0.5f * v * (1.f + erff(v * 0.70710678118654752f));
                    Cb[(size_t)row * ldc + c] = v;
                }
            }
        }
    }
}

// ---------------- softmax over rows of length kN (stride kNpad) ----------------
__global__ __launch_bounds__(256) void softmax_k(float* __restrict__ att)
{
    float* p = att + (size_t)blockIdx.x * kNpad;
    const int tid = threadIdx.x;
    __shared__ float red[256];

    float m = -1e30f;
    for (int i = tid; i < kN; i += 256) m = fmaxf(m, p[i]);
    red[tid] = m; __syncthreads();
    for (int s = 128; s > 0; s >>= 1) { if (tid < s) red[tid] = fmaxf(red[tid], red[tid + s]); __syncthreads(); }
    m = red[0]; __syncthreads();

    float s = 0.f;
    for (int i = tid; i < kN; i += 256) { float e = __expf(p[i] - m); p[i] = e; s += e; }
    red[tid] = s; __syncthreads();
    for (int st = 128; st > 0; st >>= 1) { if (tid < st) red[tid] += red[tid + st]; __syncthreads(); }
    float inv = 1.f / red[0];
    for (int i = tid; i < kN; i += 256) p[i] *= inv;
    for (int i = kN + tid; i < kNpad; i += 256) p[i] = 0.f;  // zero K-pad for AV GEMM
}

// ---------------- layernorm ----------------
__global__ __launch_bounds__(256) void ln_k(
    const float* __restrict__ x, const float* __restrict__ g,
    const float* __restrict__ bb, float* __restrict__ y)
{
    const int row = blockIdx.x, tid = threadIdx.x;
    const float* xr = x + (size_t)row * kD;
    float v[4]; float s = 0.f;
#pragma unroll
    for (int i = 0; i < 4; i++) { v[i] = xr[tid + i * 256]; s += v[i]; }
    __shared__ float red[256];
    red[tid] = s; __syncthreads();
    for (int st = 128; st > 0; st >>= 1) { if (tid < st) red[tid] += red[tid + st]; __syncthreads(); }
    float mean = red[0] * (1.f / kD); __syncthreads();
    float sq = 0.f;
#pragma unroll
    for (int i = 0; i < 4; i++) { float d = v[i] - mean; sq += d * d; }
    red[tid] = sq; __syncthreads();
    for (int st = 128; st > 0; st >>= 1) { if (tid < st) red[tid] += red[tid + st]; __syncthreads(); }
    float inv = rsqrtf(red[0] * (1.f / kD) + 1e-6f);
    float* yr = y + (size_t)row * kD;
#pragma unroll
    for (int i = 0; i < 4; i++) { int c = tid + i * 256; yr[c] = (v[i] - mean) * inv * g[c] + bb[c]; }
}

// ---------------- small helpers ----------------
__global__ void im2col_k(const float* __restrict__ x, float* __restrict__ col)
{
    int idx = blockIdx.x * 256 + threadIdx.x;
    if (idx >= kB * kNP * kKP) return;
    int kk = idx % kKP; int m = idx / kKP;
    int b = m / kNP; int pi = m % kNP;
    int gh = pi / kGH; int gw = pi % kGH;
    int c = kk / (kP * kP); int rr = (kk % (kP * kP)) / kP; int q = kk % kP;
    col[idx] = x[(((size_t)b * kCIN + c) * kIMG + gh * kP + rr) * kIMG + gw * kP + q];
}

__global__ void wpt_k(const float* __restrict__ Wp, float* __restrict__ wt)
{
    int idx = blockIdx.x * 256 + threadIdx.x;
    if (idx >= kKP * kD) return;
    int d = idx % kD; int k = idx / kD;
    wt[idx] = Wp[(size_t)d * kKP + k];
}

__global__ void assemble_k(const float* __restrict__ tok, const float* __restrict__ cls,
                           const float* __restrict__ pos, float* __restrict__ h)
{
    int idx = blockIdx.x * 256 + threadIdx.x;
    if (idx >= kM * kD) return;
    int d = idx % kD; int rem = idx / kD; int n = rem % kN; int b = rem / kN;
    float v = (n == 0) ? cls[d] : tok[((size_t)b * kNP + (n - 1)) * kD + d];
    h[idx] = v + pos[(size_t)n * kD + d];
}

__global__ void copy_k(const float* __restrict__ src, float* __restrict__ dst, int n)
{
    int idx = blockIdx.x * 256 + threadIdx.x;
    if (idx < n) dst[idx] = src[idx];
}

// ---------------- launch ----------------
extern "C" void kernel_launch(void* const* d_in, const int* in_sizes, int n_in,
                              void* d_out, int out_size)
{
    (void)in_sizes; (void)n_in; (void)out_size;
    const float* x    = (const float*)d_in[0];
    const float* Wp   = (const float*)d_in[1];
    const float* bp   = (const float*)d_in[2];
    const float* cls  = (const float*)d_in[3];
    const float* pos  = (const float*)d_in[4];
    const float* g1   = (const float*)d_in[5];
    const float* b1   = (const float*)d_in[6];
    const float* Wqkv = (const float*)d_in[7];
    const float* bqkv = (const float*)d_in[8];
    const float* Wo   = (const float*)d_in[9];
    const float* bo   = (const float*)d_in[10];
    const float* g2   = (const float*)d_in[11];
    const float* b2   = (const float*)d_in[12];
    const float* W1   = (const float*)d_in[13];
    const float* b1m  = (const float*)d_in[14];
    const float* W2   = (const float*)d_in[15];
    const float* b2m  = (const float*)d_in[16];

    float *h, *y, *qkv, *att, *o, *hid, *wpT, *colb;
    cudaGetSymbolAddress((void**)&h,    g_h);
    cudaGetSymbolAddress((void**)&y,    g_y);
    cudaGetSymbolAddress((void**)&qkv,  g_qkv);
    cudaGetSymbolAddress((void**)&att,  g_att);
    cudaGetSymbolAddress((void**)&o,    g_o);
    cudaGetSymbolAddress((void**)&hid,  g_hid);
    cudaGetSymbolAddress((void**)&wpT,  g_wpT);
    cudaGetSymbolAddress((void**)&colb, g_col);

    // ---- patch embed ----
    im2col_k<<<(kB * kNP * kKP + 255) / 256, 256>>>(x, colb);
    wpt_k<<<(kKP * kD + 255) / 256, 256>>>(Wp, wpT);
    {
        dim3 grid(kD / 128, (kB * kNP + 127) / 128, 1);
        mm_tf32<EP_BIAS, false><<<grid, 256>>>(
            colb, kKP, 0, 0, wpT, kD, 0, 0, bp, nullptr,
            y, kD, 0, 0, kB * kNP, kD, kKP, 1, 1.f);
    }
    assemble_k<<<(kM * kD + 255) / 256, 256>>>(y, cls, pos, h);

    const long sTokB = (long)kN * 3 * kD;  // qkv batch stride
    const long sAttB = (long)kH * kN * kNpad;
    const long sAttH = (long)kN * kNpad;
    const long sOB = (long)kN * kD;

    for (int l = 0; l < kDEPTH; l++) {
        ln_k<<<kM, 256>>>(h, g1 + (size_t)l * kD, b1 + (size_t)l * kD, y);
        {   // QKV
            dim3 grid(3 * kD / 128, (kM + 127) / 128, 1);
            mm_tf32<EP_BIAS, false><<<grid, 256>>>(
                y, kD, 0, 0, Wqkv + (size_t)l * kD * 3 * kD, 3 * kD, 0, 0,
                bqkv + (size_t)l * 3 * kD, nullptr,
                qkv, 3 * kD, 0, 0, kM, 3 * kD, kD, 1, 1.f);
        }
        {   // scores = scale * q @ k^T   (batched over b,h)
            dim3 grid((kN + 127) / 128, (kN + 127) / 128, kB * kH);
            mm_tf32<EP_SCALE, true><<<grid, 256>>>(
                qkv, 3 * kD, sTokB, kHD,
                qkv + kD, 3 * kD, sTokB, kHD,
                nullptr, nullptr,
                att, kNpad, sAttB, sAttH,
                kN, kN, kHD, kH, kScale);
        }
        softmax_k<<<kB * kH * kN, 256>>>(att);
        {   // o = att @ v
            dim3 grid(1, (kN + 127) / 128, kB * kH);
            mm_tf32<EP_NONE, false><<<grid, 256>>>(
                att, kNpad, sAttB, sAttH,
                qkv + 2 * kD, 3 * kD, sTokB, kHD,
                nullptr, nullptr,
                o, kD, sOB, kHD,
                kN, kHD, kNpad, kH, 1.f);
        }
        {   // O projection + residual
            dim3 grid(kD / 128, (kM + 127) / 128, 1);
            mm_tf32<EP_RESID, false><<<grid, 256>>>(
                o, kD, 0, 0, Wo + (size_t)l * kD * kD, kD, 0, 0,
                bo + (size_t)l * kD, h,
                h, kD, 0, 0, kM, kD, kD, 1, 1.f);
        }
        ln_k<<<kM, 256>>>(h, g2 + (size_t)l * kD, b2 + (size_t)l * kD, y);
        {   // FF1 + GELU
            dim3 grid(kDFF / 128, (kM + 127) / 128, 1);
            mm_tf32<EP_GELU, false><<<grid, 256>>>(
                y, kD, 0, 0, W1 + (size_t)l * kD * kDFF, kDFF, 0, 0,
                b1m + (size_t)l * kDFF, nullptr,
                hid, kDFF, 0, 0, kM, kDFF, kD, 1, 1.f);
        }
        {   // FF2 + residual
            dim3 grid(kD / 128, (kM + 127) / 128, 1);
            mm_tf32<EP_RESID, false><<<grid, 256>>>(
                hid, kDFF, 0, 0, W2 + (size_t)l * kDFF * kD, kD, 0, 0,
                b2m + (size_t)l * kD, h,
                h, kD, 0, 0, kM, kD, kDFF, 1, 1.f);
        }
    }

    copy_k<<<(kM * kD + 255) / 256, 256>>>(h, (float*)d_out, kM * kD);
}